// round 12
// baseline (speedup 1.0000x reference)
#include <cuda_runtime.h>
#include <cuda_fp16.h>

#define B_    128
#define IN_   1024
#define OUT_  1024

constexpr float BETA    = 0.99f;
constexpr float THRESH  = 1.0f;
constexpr float RESETV  = 0.8f;
constexpr float INV_TAU = 0.05f;              // 1/20
constexpr float A_SC    = 0.005f / 128.0f;    // A / B

// ---- device scratch (static, allocation-free) ------------------------------
__device__ float g_Wt[IN_ * OUT_];            // Wt[k][o] = W[o][k]
__device__ int   g_sIdx[B_ * 256];            // spiking-k indices per batch (ordered)
__device__ int   g_sCnt[B_];
// Ipk slot layout: within each 64-i group g, i=(g*64+r) stored at uint2 slot
// g*64 + (r&31)*2 + (r>>5)  ->  (i, i+32) adjacent uint2 = one uint4.
__device__ uint2 g_Ipk[B_ * IN_];             // (p2, q2): e^{+dp/20}, e^{-dp/20}
__device__ uint2 g_Opk[B_ * OUT_ / 2];        // per o-pair (r2, -s2)

__device__ __forceinline__ __half2 u2h(unsigned u) { return *reinterpret_cast<__half2*>(&u); }
__device__ __forceinline__ unsigned h2u(__half2 h) { return *reinterpret_cast<unsigned*>(&h); }

// ---------------------------------------------------------------------------
// Front kernel:
//  [0,256)    transpose W -> Wt. Fat blocks: 32 o-rows x 128 k (4 tiles),
//             all 4 LDG.128 issued up-front (MLP=4), one sync, 4 store rounds.
//  [256,768)  Ipack;  [768,896) spike-index compaction.
// ---------------------------------------------------------------------------
__global__ __launch_bounds__(256) void k_front(
    const float* __restrict__ W,
    const float* __restrict__ spikes,
    const float* __restrict__ dpre)
{
    if (blockIdx.x < 256) {
        __shared__ float t[4][32][33];           // 16.9 KB, conflict-free
        const int by  = (blockIdx.x >> 3) * 32;  // o-tile (32 of them)
        const int bx0 = (blockIdx.x & 7) * 128;  // k-strip (8 of them)
        const int c8 = threadIdx.x & 7;          // float4 column
        const int rw = threadIdx.x >> 3;         // row 0..31

        float4 v[4];
        #pragma unroll
        for (int s = 0; s < 4; s++)              // 4 independent LDG.128
            v[s] = *reinterpret_cast<const float4*>(
                &W[(size_t)(by + rw) * IN_ + bx0 + s * 32 + c8 * 4]);
        #pragma unroll
        for (int s = 0; s < 4; s++) {
            t[s][rw][c8 * 4 + 0] = v[s].x;
            t[s][rw][c8 * 4 + 1] = v[s].y;
            t[s][rw][c8 * 4 + 2] = v[s].z;
            t[s][rw][c8 * 4 + 3] = v[s].w;
        }
        __syncthreads();
        #pragma unroll
        for (int s = 0; s < 4; s++) {
            float4 o4 = make_float4(t[s][c8 * 4 + 0][rw], t[s][c8 * 4 + 1][rw],
                                    t[s][c8 * 4 + 2][rw], t[s][c8 * 4 + 3][rw]);
            *reinterpret_cast<float4*>(
                &g_Wt[(size_t)(bx0 + s * 32 + rw) * OUT_ + by + c8 * 4]) = o4;
        }
    } else if (blockIdx.x < 768) {
        int idx = (blockIdx.x - 256) * 256 + threadIdx.x;  // b*IN_ + i
        float dp = (spikes[idx] > 0.0f) ? 0.0f : dpre[idx] + 1.0f;
        uint2 u;
        u.x = h2u(__float2half2_rn(__expf(dp * INV_TAU)));   // p pair
        u.y = h2u(__float2half2_rn(__expf(-dp * INV_TAU)));  // q pair
        int i = idx & (IN_ - 1);
        int b = idx >> 10;
        int g = i >> 6, r = i & 63;
        int slot = (g << 6) + ((r & 31) << 1) + (r >> 5);
        g_Ipk[b * IN_ + slot] = u;
    } else {
        // spike-index compaction for batch b (deterministic, order-preserving)
        __shared__ int wsum[8];
        __shared__ int wbase[8];
        const int b = blockIdx.x - 768;
        const int tid = threadIdx.x;
        const int lane = tid & 31, wid = tid >> 5;

        float4 sp = reinterpret_cast<const float4*>(spikes)[b * 256 + tid];
        int f0 = sp.x > 0.0f, f1 = sp.y > 0.0f, f2 = sp.z > 0.0f, f3 = sp.w > 0.0f;
        int c = f0 + f1 + f2 + f3;

        int s = c;                                 // inclusive warp scan
        #pragma unroll
        for (int d = 1; d < 32; d <<= 1) {
            int v = __shfl_up_sync(0xFFFFFFFFu, s, d);
            if (lane >= d) s += v;
        }
        if (lane == 31) wsum[wid] = s;
        __syncthreads();
        if (tid == 0) {
            int acc = 0;
            #pragma unroll
            for (int w = 0; w < 8; w++) { wbase[w] = acc; acc += wsum[w]; }
            g_sCnt[b] = acc;
        }
        __syncthreads();

        int base = wbase[wid] + (s - c);           // exclusive offset
        int k0 = tid * 4;
        int* dst = &g_sIdx[b * 256];
        if (f0) dst[base++] = k0;
        if (f1) dst[base++] = k0 + 1;
        if (f2) dst[base++] = k0 + 2;
        if (f3) dst[base  ] = k0 + 3;
    }
}

// ---------------------------------------------------------------------------
// Fused sparse matmul + LIF + Opack.
// grid (2 o-chunks of 512, 128 b). 256 threads, thread = one o-PAIR (float2).
// ---------------------------------------------------------------------------
__global__ __launch_bounds__(256) void k_mm_lif(
    const float* __restrict__ membrane, const float* __restrict__ dfire,
    float* __restrict__ out_spike, float* __restrict__ out_mem)
{
    __shared__ int sk[256];
    const int tid = threadIdx.x;
    const int b = blockIdx.y;
    const int o0 = blockIdx.x * 512 + tid * 2;    // even o

    const int cnt = g_sCnt[b];
    if (tid < cnt) sk[tid] = g_sIdx[b * 256 + tid];
    __syncthreads();

    float2 a0 = make_float2(0.f, 0.f), a1 = make_float2(0.f, 0.f);
    float2 a2 = make_float2(0.f, 0.f), a3 = make_float2(0.f, 0.f);
    int j = 0;
    for (; j + 4 <= cnt; j += 4) {
        int k0 = sk[j], k1 = sk[j + 1], k2 = sk[j + 2], k3 = sk[j + 3];
        float2 w0 = *reinterpret_cast<const float2*>(&g_Wt[(size_t)k0 * OUT_ + o0]);
        float2 w1 = *reinterpret_cast<const float2*>(&g_Wt[(size_t)k1 * OUT_ + o0]);
        float2 w2 = *reinterpret_cast<const float2*>(&g_Wt[(size_t)k2 * OUT_ + o0]);
        float2 w3 = *reinterpret_cast<const float2*>(&g_Wt[(size_t)k3 * OUT_ + o0]);
        a0.x += w0.x; a0.y += w0.y;
        a1.x += w1.x; a1.y += w1.y;
        a2.x += w2.x; a2.y += w2.y;
        a3.x += w3.x; a3.y += w3.y;
    }
    for (; j < cnt; j++) {
        float2 w = *reinterpret_cast<const float2*>(&g_Wt[(size_t)sk[j] * OUT_ + o0]);
        a0.x += w.x; a0.y += w.y;
    }
    float w0 = (a0.x + a1.x) + (a2.x + a3.x);
    float w1 = (a0.y + a1.y) + (a2.y + a3.y);

    const int base = b * OUT_ + o0;
    float2 mem = *reinterpret_cast<const float2*>(&membrane[base]);
    float2 dfr = *reinterpret_cast<const float2*>(&dfire[base]);

    float m0 = mem.x * BETA + w0, m1 = mem.y * BETA + w1;
    float s0 = (m0 > THRESH) ? 1.0f : 0.0f;
    float s1 = (m1 > THRESH) ? 1.0f : 0.0f;
    if (s0 > 0.f) m0 -= RESETV;
    if (s1 > 0.f) m1 -= RESETV;

    *reinterpret_cast<float2*>(&out_spike[base]) = make_float2(s0, s1);
    *reinterpret_cast<float2*>(&out_mem[base])   = make_float2(m0, m1);

    float df0 = (s0 > 0.f) ? 0.0f : dfr.x + 1.0f;
    float df1 = (s1 > 0.f) ? 0.0f : dfr.y + 1.0f;
    uint2 u;
    u.x = h2u(__floats2half2_rn(__expf(-df0 * INV_TAU), __expf(-df1 * INV_TAU)));  // r
    u.y = h2u(__floats2half2_rn(-__expf(df0 * INV_TAU), -__expf(df1 * INV_TAU))); // -s
    g_Opk[base >> 1] = u;
}

// ---------------------------------------------------------------------------
// STDP via product-vs-1 test (exact at dp==df):
//   t1 = p*r < 1  <=> df > dp : contribute +t1
//   t2 = q*(-s) > -1 <=> df < dp : contribute t2
// Tile 64i x 16o, grid (64 o-blk, 16 i-blk) = 1024 blocks, 128 threads.
// Inner b-loop register-prefetched ((b+1)&15 -> branch-free).
// ---------------------------------------------------------------------------
__global__ __launch_bounds__(128) void k_stdp(
    const float* __restrict__ W, float* __restrict__ outW)
{
    __shared__ uint4 sI[16][32];   // 8 KB: (p,q) for i=j and i=j+32
    __shared__ uint4 sO[16][4];    // 1 KB: o-quads

    const int tid = threadIdx.x;
    const int tx = tid & 31;       // lane -> i (and i+32)
    const int wp = tid >> 5;       // warp (0..3) -> o-quad
    const int oBase = blockIdx.x * 16;
    const int iBase = blockIdx.y * 64;

    const __half2 ONE  = __float2half2_rn(1.0f);
    const __half2 NEG1 = __float2half2_rn(-1.0f);

    float accf[2][2][2];           // [i-half][o-pair][lo/hi]
    #pragma unroll
    for (int j = 0; j < 2; j++)
        #pragma unroll
        for (int c = 0; c < 2; c++) { accf[j][c][0] = 0.f; accf[j][c][1] = 0.f; }

    const uint4* Ipk4 = reinterpret_cast<const uint4*>(g_Ipk);
    const uint4* Opk4 = reinterpret_cast<const uint4*>(g_Opk);

    for (int cb = 0; cb < 8; cb++) {           // 8 chunks of 16 batches
        // sI: 16 b x 32 uint4 = 512; 4 per thread, coalesced LDG.128
        #pragma unroll
        for (int t = tid; t < 512; t += 128) {
            int b = t >> 5, j = t & 31;
            sI[b][j] = Ipk4[((cb * 16 + b) * IN_ + iBase) / 2 + j];
        }
        // sO: 16 b x 4 uint4 = 64
        if (tid < 64) {
            int b = tid >> 2, j = tid & 3;
            sO[b][j] = Opk4[(cb * 16 + b) * (OUT_ / 4) + (oBase >> 2) + j];
        }
        __syncthreads();

        __half2 acch[2][2];
        #pragma unroll
        for (int j = 0; j < 2; j++) {
            acch[j][0] = __float2half2_rn(0.f);
            acch[j][1] = __float2half2_rn(0.f);
        }

        // software-pipelined: branch-free prefetch of (b+1)&15
        uint4 iv = sI[0][tx];
        uint4 ov = sO[0][wp];
        #pragma unroll
        for (int b = 0; b < 16; b++) {
            int bn = (b + 1) & 15;
            uint4 ivn = sI[bn][tx];            // LDS.128 conflict-free
            uint4 ovn = sO[bn][wp];            // LDS.128 broadcast
            __half2 pq[2][2] = {{u2h(iv.x), u2h(iv.y)}, {u2h(iv.z), u2h(iv.w)}};
            __half2 rs[2][2] = {{u2h(ov.x), u2h(ov.y)}, {u2h(ov.z), u2h(ov.w)}};
            #pragma unroll
            for (int j = 0; j < 2; j++) {      // i-half
                #pragma unroll
                for (int c = 0; c < 2; c++) {  // o-pair
                    __half2 t1 = __hmul2(pq[j][0], rs[c][0]);
                    __half2 t2 = __hmul2(pq[j][1], rs[c][1]);
                    __half2 m1 = __hlt2(t1, ONE);
                    __half2 m2 = __hgt2(t2, NEG1);
                    acch[j][c] = __hfma2(m1, t1, acch[j][c]);
                    acch[j][c] = __hfma2(m2, t2, acch[j][c]);
                }
            }
            iv = ivn; ov = ovn;
        }

        #pragma unroll
        for (int j = 0; j < 2; j++)
            #pragma unroll
            for (int c = 0; c < 2; c++) {
                accf[j][c][0] += __low2float(acch[j][c]);
                accf[j][c][1] += __high2float(acch[j][c]);
            }
        __syncthreads();
    }

    // epilogue: lanes along i -> 128B coalesced stores
    #pragma unroll
    for (int j = 0; j < 2; j++) {
        const int i = iBase + j * 32 + tx;
        #pragma unroll
        for (int c = 0; c < 2; c++) {
            #pragma unroll
            for (int h = 0; h < 2; h++) {
                int o = oBase + wp * 4 + c * 2 + h;
                size_t off = (size_t)o * IN_ + i;
                outW[off] = W[off] + accf[j][c][h] * A_SC;
            }
        }
    }
}

// ---------------------------------------------------------------------------
extern "C" void kernel_launch(void* const* d_in, const int* in_sizes, int n_in,
                              void* d_out, int out_size)
{
    const float* spikes   = (const float*)d_in[0];
    const float* W        = (const float*)d_in[1];
    const float* membrane = (const float*)d_in[2];
    const float* dpre     = (const float*)d_in[3];
    const float* dfire    = (const float*)d_in[4];

    float* out       = (float*)d_out;
    float* out_spike = out;                                   // (B, OUT)
    float* out_W     = out + B_ * OUT_;                       // (OUT, IN)
    float* out_mem   = out + B_ * OUT_ + (size_t)OUT_ * IN_;  // (B, OUT)

    k_front<<<896, 256>>>(W, spikes, dpre);
    k_mm_lif<<<dim3(2, 128), 256>>>(membrane, dfire, out_spike, out_mem);
    k_stdp<<<dim3(64, 16), 128>>>(W, out_W);
}

// round 13
// speedup vs baseline: 1.0009x; 1.0009x over previous
#include <cuda_runtime.h>
#include <cuda_fp16.h>

#define B_    128
#define IN_   1024
#define OUT_  1024

constexpr float BETA    = 0.99f;
constexpr float THRESH  = 1.0f;
constexpr float RESETV  = 0.8f;
constexpr float INV_TAU = 0.05f;              // 1/20
constexpr float A_SC    = 0.005f / 128.0f;    // A / B

// ---- device scratch (static, allocation-free) ------------------------------
__device__ float g_Wt[IN_ * OUT_];            // Wt[k][o] = W[o][k]
__device__ int   g_sIdx[B_ * 256];            // spiking-k indices per batch (ordered)
__device__ int   g_sCnt[B_];
// Ipk slot layout: within each 64-i group g, i=(g*64+r) stored at uint2 slot
// g*64 + (r&31)*2 + (r>>5)  ->  (i, i+32) adjacent uint2 = one uint4.
__device__ uint2 g_Ipk[B_ * IN_];             // (p2, q2): e^{+dp/20}, e^{-dp/20}
__device__ uint2 g_Opk[B_ * OUT_ / 2];        // per o-pair (r2, -s2)

__device__ __forceinline__ __half2 u2h(unsigned u) { return *reinterpret_cast<__half2*>(&u); }
__device__ __forceinline__ unsigned h2u(__half2 h) { return *reinterpret_cast<unsigned*>(&h); }

// ---------------------------------------------------------------------------
// Front kernel (best-measured R10 version): [0,1024) transpose W -> Wt
// (32x32 scalar tiles); [1024,1536) Ipack; [1536,1664) spike compaction.
// ---------------------------------------------------------------------------
__global__ __launch_bounds__(256) void k_front(
    const float* __restrict__ W,
    const float* __restrict__ spikes,
    const float* __restrict__ dpre)
{
    if (blockIdx.x < 1024) {
        __shared__ float t[32][33];
        const int bx = (blockIdx.x & 31) * 32;   // k range
        const int by = (blockIdx.x >> 5) * 32;   // o range
        const int tx = threadIdx.x & 31;
        const int ty = threadIdx.x >> 5;         // 0..7
        #pragma unroll
        for (int i = 0; i < 32; i += 8)
            t[ty + i][tx] = W[(size_t)(by + ty + i) * IN_ + bx + tx];
        __syncthreads();
        #pragma unroll
        for (int i = 0; i < 32; i += 8)
            g_Wt[(size_t)(bx + ty + i) * OUT_ + by + tx] = t[tx][ty + i];
    } else if (blockIdx.x < 1536) {
        int idx = (blockIdx.x - 1024) * 256 + threadIdx.x;  // b*IN_ + i
        float dp = (spikes[idx] > 0.0f) ? 0.0f : dpre[idx] + 1.0f;
        uint2 u;
        u.x = h2u(__float2half2_rn(__expf(dp * INV_TAU)));   // p pair
        u.y = h2u(__float2half2_rn(__expf(-dp * INV_TAU)));  // q pair
        int i = idx & (IN_ - 1);
        int b = idx >> 10;
        int g = i >> 6, r = i & 63;
        int slot = (g << 6) + ((r & 31) << 1) + (r >> 5);
        g_Ipk[b * IN_ + slot] = u;
    } else {
        // spike-index compaction for batch b (deterministic, order-preserving)
        __shared__ int wsum[8];
        __shared__ int wbase[8];
        const int b = blockIdx.x - 1536;
        const int tid = threadIdx.x;
        const int lane = tid & 31, wid = tid >> 5;

        float4 sp = reinterpret_cast<const float4*>(spikes)[b * 256 + tid];
        int f0 = sp.x > 0.0f, f1 = sp.y > 0.0f, f2 = sp.z > 0.0f, f3 = sp.w > 0.0f;
        int c = f0 + f1 + f2 + f3;

        int s = c;                                 // inclusive warp scan
        #pragma unroll
        for (int d = 1; d < 32; d <<= 1) {
            int v = __shfl_up_sync(0xFFFFFFFFu, s, d);
            if (lane >= d) s += v;
        }
        if (lane == 31) wsum[wid] = s;
        __syncthreads();
        if (tid == 0) {
            int acc = 0;
            #pragma unroll
            for (int w = 0; w < 8; w++) { wbase[w] = acc; acc += wsum[w]; }
            g_sCnt[b] = acc;
        }
        __syncthreads();

        int base = wbase[wid] + (s - c);           // exclusive offset
        int k0 = tid * 4;
        int* dst = &g_sIdx[b * 256];
        if (f0) dst[base++] = k0;
        if (f1) dst[base++] = k0 + 1;
        if (f2) dst[base++] = k0 + 2;
        if (f3) dst[base  ] = k0 + 3;
    }
}

// ---------------------------------------------------------------------------
// Fused sparse matmul + LIF + Opack. (unchanged, L2-bound at its floor)
// grid (2 o-chunks of 512, 128 b). 256 threads, thread = one o-PAIR (float2).
// ---------------------------------------------------------------------------
__global__ __launch_bounds__(256) void k_mm_lif(
    const float* __restrict__ membrane, const float* __restrict__ dfire,
    float* __restrict__ out_spike, float* __restrict__ out_mem)
{
    __shared__ int sk[256];
    const int tid = threadIdx.x;
    const int b = blockIdx.y;
    const int o0 = blockIdx.x * 512 + tid * 2;    // even o

    const int cnt = g_sCnt[b];
    if (tid < cnt) sk[tid] = g_sIdx[b * 256 + tid];
    __syncthreads();

    float2 a0 = make_float2(0.f, 0.f), a1 = make_float2(0.f, 0.f);
    float2 a2 = make_float2(0.f, 0.f), a3 = make_float2(0.f, 0.f);
    int j = 0;
    for (; j + 4 <= cnt; j += 4) {
        int k0 = sk[j], k1 = sk[j + 1], k2 = sk[j + 2], k3 = sk[j + 3];
        float2 w0 = *reinterpret_cast<const float2*>(&g_Wt[(size_t)k0 * OUT_ + o0]);
        float2 w1 = *reinterpret_cast<const float2*>(&g_Wt[(size_t)k1 * OUT_ + o0]);
        float2 w2 = *reinterpret_cast<const float2*>(&g_Wt[(size_t)k2 * OUT_ + o0]);
        float2 w3 = *reinterpret_cast<const float2*>(&g_Wt[(size_t)k3 * OUT_ + o0]);
        a0.x += w0.x; a0.y += w0.y;
        a1.x += w1.x; a1.y += w1.y;
        a2.x += w2.x; a2.y += w2.y;
        a3.x += w3.x; a3.y += w3.y;
    }
    for (; j < cnt; j++) {
        float2 w = *reinterpret_cast<const float2*>(&g_Wt[(size_t)sk[j] * OUT_ + o0]);
        a0.x += w.x; a0.y += w.y;
    }
    float w0 = (a0.x + a1.x) + (a2.x + a3.x);
    float w1 = (a0.y + a1.y) + (a2.y + a3.y);

    const int base = b * OUT_ + o0;
    float2 mem = *reinterpret_cast<const float2*>(&membrane[base]);
    float2 dfr = *reinterpret_cast<const float2*>(&dfire[base]);

    float m0 = mem.x * BETA + w0, m1 = mem.y * BETA + w1;
    float s0 = (m0 > THRESH) ? 1.0f : 0.0f;
    float s1 = (m1 > THRESH) ? 1.0f : 0.0f;
    if (s0 > 0.f) m0 -= RESETV;
    if (s1 > 0.f) m1 -= RESETV;

    *reinterpret_cast<float2*>(&out_spike[base]) = make_float2(s0, s1);
    *reinterpret_cast<float2*>(&out_mem[base])   = make_float2(m0, m1);

    float df0 = (s0 > 0.f) ? 0.0f : dfr.x + 1.0f;
    float df1 = (s1 > 0.f) ? 0.0f : dfr.y + 1.0f;
    uint2 u;
    u.x = h2u(__floats2half2_rn(__expf(-df0 * INV_TAU), __expf(-df1 * INV_TAU)));  // r
    u.y = h2u(__floats2half2_rn(-__expf(df0 * INV_TAU), -__expf(df1 * INV_TAU))); // -s
    g_Opk[base >> 1] = u;
}

// ---------------------------------------------------------------------------
// STDP via product-vs-1 test (exact at dp==df):
//   t1 = p*r < 1  <=> df > dp : contribute +t1
//   t2 = q*(-s) > -1 <=> df < dp : contribute t2
// Tile 64i x 16o, grid (64 o-blk, 16 i-blk) = 1024 blocks, 128 threads.
// 32-batch chunks (4 total): halves sync/flush/staging-loop overhead vs 16-b.
// Inner b-loop register-prefetched, unroll 8 (body fits L0 I-cache).
// ---------------------------------------------------------------------------
__global__ __launch_bounds__(128) void k_stdp(
    const float* __restrict__ W, float* __restrict__ outW)
{
    __shared__ uint4 sI[32][32];   // 16 KB: (p,q) for i=j and i=j+32
    __shared__ uint4 sO[32][4];    //  2 KB: o-quads

    const int tid = threadIdx.x;
    const int tx = tid & 31;       // lane -> i (and i+32)
    const int wp = tid >> 5;       // warp (0..3) -> o-quad
    const int oBase = blockIdx.x * 16;
    const int iBase = blockIdx.y * 64;

    const __half2 ONE  = __float2half2_rn(1.0f);
    const __half2 NEG1 = __float2half2_rn(-1.0f);

    float accf[2][2][2];           // [i-half][o-pair][lo/hi]
    #pragma unroll
    for (int j = 0; j < 2; j++)
        #pragma unroll
        for (int c = 0; c < 2; c++) { accf[j][c][0] = 0.f; accf[j][c][1] = 0.f; }

    const uint4* Ipk4 = reinterpret_cast<const uint4*>(g_Ipk);
    const uint4* Opk4 = reinterpret_cast<const uint4*>(g_Opk);

    for (int cb = 0; cb < 4; cb++) {           // 4 chunks of 32 batches
        // sI: 32 b x 32 uint4 = 1024; 8 per thread, coalesced LDG.128
        #pragma unroll
        for (int t = tid; t < 1024; t += 128) {
            int b = t >> 5, j = t & 31;
            sI[b][j] = Ipk4[((cb * 32 + b) * IN_ + iBase) / 2 + j];
        }
        // sO: 32 b x 4 uint4 = 128; 1 per thread
        {
            int b = tid >> 2, j = tid & 3;
            sO[b][j] = Opk4[(cb * 32 + b) * (OUT_ / 4) + (oBase >> 2) + j];
        }
        __syncthreads();

        __half2 acch[2][2];
        #pragma unroll
        for (int j = 0; j < 2; j++) {
            acch[j][0] = __float2half2_rn(0.f);
            acch[j][1] = __float2half2_rn(0.f);
        }

        // software-pipelined: branch-free prefetch of (b+1)&31
        uint4 iv = sI[0][tx];
        uint4 ov = sO[0][wp];
        #pragma unroll 8
        for (int b = 0; b < 32; b++) {
            int bn = (b + 1) & 31;
            uint4 ivn = sI[bn][tx];            // LDS.128 conflict-free
            uint4 ovn = sO[bn][wp];            // LDS.128 broadcast
            __half2 pq[2][2] = {{u2h(iv.x), u2h(iv.y)}, {u2h(iv.z), u2h(iv.w)}};
            __half2 rs[2][2] = {{u2h(ov.x), u2h(ov.y)}, {u2h(ov.z), u2h(ov.w)}};
            #pragma unroll
            for (int j = 0; j < 2; j++) {      // i-half
                #pragma unroll
                for (int c = 0; c < 2; c++) {  // o-pair
                    __half2 t1 = __hmul2(pq[j][0], rs[c][0]);
                    __half2 t2 = __hmul2(pq[j][1], rs[c][1]);
                    __half2 m1 = __hlt2(t1, ONE);
                    __half2 m2 = __hgt2(t2, NEG1);
                    acch[j][c] = __hfma2(m1, t1, acch[j][c]);
                    acch[j][c] = __hfma2(m2, t2, acch[j][c]);
                }
            }
            iv = ivn; ov = ovn;
        }

        #pragma unroll
        for (int j = 0; j < 2; j++)
            #pragma unroll
            for (int c = 0; c < 2; c++) {
                accf[j][c][0] += __low2float(acch[j][c]);
                accf[j][c][1] += __high2float(acch[j][c]);
            }
        __syncthreads();
    }

    // epilogue: lanes along i -> 128B coalesced stores
    #pragma unroll
    for (int j = 0; j < 2; j++) {
        const int i = iBase + j * 32 + tx;
        #pragma unroll
        for (int c = 0; c < 2; c++) {
            #pragma unroll
            for (int h = 0; h < 2; h++) {
                int o = oBase + wp * 4 + c * 2 + h;
                size_t off = (size_t)o * IN_ + i;
                outW[off] = W[off] + accf[j][c][h] * A_SC;
            }
        }
    }
}

// ---------------------------------------------------------------------------
extern "C" void kernel_launch(void* const* d_in, const int* in_sizes, int n_in,
                              void* d_out, int out_size)
{
    const float* spikes   = (const float*)d_in[0];
    const float* W        = (const float*)d_in[1];
    const float* membrane = (const float*)d_in[2];
    const float* dpre     = (const float*)d_in[3];
    const float* dfire    = (const float*)d_in[4];

    float* out       = (float*)d_out;
    float* out_spike = out;                                   // (B, OUT)
    float* out_W     = out + B_ * OUT_;                       // (OUT, IN)
    float* out_mem   = out + B_ * OUT_ + (size_t)OUT_ * IN_;  // (B, OUT)

    k_front<<<1664, 256>>>(W, spikes, dpre);
    k_mm_lif<<<dim3(2, 128), 256>>>(membrane, dfire, out_spike, out_mem);
    k_stdp<<<dim3(64, 16), 128>>>(W, out_W);
}